// round 1
// baseline (speedup 1.0000x reference)
#include <cuda_runtime.h>
#include <math.h>

// Problem constants
#define BB 2
#define TT 2048
#define EE 1024
#define HH 16
#define KVH 4
#define HD 64
#define GG 4           // H / KVH
#define MM (BB*TT)     // 4096 rows

// Device scratch (allocation-free rule: __device__ globals)
__device__ float g_q[BB*TT*EE];          // 16 MiB
__device__ float g_k[BB*TT*KVH*HD];      // 4 MiB
__device__ float g_v[BB*TT*KVH*HD];      // 4 MiB
__device__ float g_y[BB*TT*EE];          // 16 MiB

// ---------------------------------------------------------------------------
// GEMM: C[M,N] = sum_k A[m,k] * W[n,k]   (A: MxK row-major, W: NxK row-major)
// 64x64 block tile, BK=16, 256 threads, 4x4 per thread.
// ---------------------------------------------------------------------------
__global__ __launch_bounds__(256) void gemm_atb(
    const float* __restrict__ A, const float* __restrict__ W,
    float* __restrict__ C, int M, int N, int K)
{
    __shared__ float As[16][65];   // [k][m], padded (conflict-free store)
    __shared__ float Ws[16][65];   // [k][n]

    const int tid = threadIdx.x;
    const int tx  = tid & 15;      // column group
    const int ty  = tid >> 4;      // row group
    const int m0  = blockIdx.y * 64;
    const int n0  = blockIdx.x * 64;

    float acc[4][4];
    #pragma unroll
    for (int i = 0; i < 4; i++)
        #pragma unroll
        for (int j = 0; j < 4; j++) acc[i][j] = 0.f;

    for (int k0 = 0; k0 < K; k0 += 16) {
        #pragma unroll
        for (int p = 0; p < 4; p++) {
            int idx = tid + p * 256;        // 0..1023
            int r = idx >> 4;               // 0..63
            int c = idx & 15;               // 0..15
            As[c][r] = A[(size_t)(m0 + r) * K + k0 + c];
            Ws[c][r] = W[(size_t)(n0 + r) * K + k0 + c];
        }
        __syncthreads();

        #pragma unroll
        for (int kk = 0; kk < 16; kk++) {
            float a[4], b[4];
            #pragma unroll
            for (int i = 0; i < 4; i++) a[i] = As[kk][ty * 4 + i];
            #pragma unroll
            for (int j = 0; j < 4; j++) b[j] = Ws[kk][tx * 4 + j];
            #pragma unroll
            for (int i = 0; i < 4; i++)
                #pragma unroll
                for (int j = 0; j < 4; j++)
                    acc[i][j] = fmaf(a[i], b[j], acc[i][j]);
        }
        __syncthreads();
    }

    #pragma unroll
    for (int i = 0; i < 4; i++) {
        float4 out = make_float4(acc[i][0], acc[i][1], acc[i][2], acc[i][3]);
        *reinterpret_cast<float4*>(
            &C[(size_t)(m0 + ty * 4 + i) * N + n0 + tx * 4]) = out;
    }
}

// ---------------------------------------------------------------------------
// RoPE in-place: x layout [b*T + t][heads*64], cos/sin layout [b*T + t][64]
// One thread per (bt, head, d in [0,32)).
// ---------------------------------------------------------------------------
__global__ void rope_kernel(float* __restrict__ x,
                            const float* __restrict__ c,
                            const float* __restrict__ s,
                            int heads, int n)
{
    int idx = blockIdx.x * blockDim.x + threadIdx.x;
    if (idx >= n) return;
    int d  = idx & 31;
    int r  = idx >> 5;
    int h  = r % heads;
    int bt = r / heads;

    float* p = x + ((size_t)bt * heads + h) * 64;
    const float* cp = c + (size_t)bt * 64;
    const float* sp = s + (size_t)bt * 64;

    float x1 = p[d];
    float x2 = p[d + 32];
    p[d]      = x1 * cp[d]      - x2 * sp[d];
    p[d + 32] = x2 * cp[d + 32] + x1 * sp[d + 32];
}

// ---------------------------------------------------------------------------
// Causal flash attention, fp32, BM=BN=64, HD=64.
// grid = (T/64, H, B), block = 256 (16x16 thread tile, 4x4 per thread).
// Dynamic smem: Qs[64][64], Ks[64][65], Vs[64][64], Ps[64][64].
// ---------------------------------------------------------------------------
__global__ __launch_bounds__(256) void flash_attn(
    const float* __restrict__ q, const float* __restrict__ k,
    const float* __restrict__ v, float* __restrict__ y)
{
    extern __shared__ float sm[];
    float (*Qs)[64] = (float(*)[64])(sm);
    float (*Ks)[65] = (float(*)[65])(sm + 64 * 64);
    float (*Vs)[64] = (float(*)[64])(sm + 64 * 64 + 64 * 65);
    float (*Ps)[64] = (float(*)[64])(sm + 64 * 64 + 64 * 65 + 64 * 64);

    const int tid = threadIdx.x;
    const int tx  = tid & 15;
    const int ty  = tid >> 4;
    const int qt  = blockIdx.x;
    const int h   = blockIdx.y;
    const int b   = blockIdx.z;
    const int kvh = h / GG;
    const float scale = 0.125f;   // 1/sqrt(64)

    // Load Q tile (64 rows x 64 dims)
    #pragma unroll
    for (int p = 0; p < 16; p++) {
        int idx = tid + p * 256;
        int r = idx >> 6, c = idx & 63;
        Qs[r][c] = q[(size_t)(b * TT + qt * 64 + r) * EE + h * 64 + c];
    }

    float m[4], l[4], o[4][4];
    #pragma unroll
    for (int i = 0; i < 4; i++) {
        m[i] = -INFINITY; l[i] = 0.f;
        #pragma unroll
        for (int j = 0; j < 4; j++) o[i][j] = 0.f;
    }

    for (int kt = 0; kt <= qt; kt++) {
        __syncthreads();   // protect Ks/Vs (prev PV done) and Qs on first iter
        #pragma unroll
        for (int p = 0; p < 16; p++) {
            int idx = tid + p * 256;
            int r = idx >> 6, c = idx & 63;
            size_t base = (size_t)(b * TT + kt * 64 + r) * (KVH * HD) + kvh * 64 + c;
            Ks[r][c] = k[base];
            Vs[r][c] = v[base];
        }
        __syncthreads();

        // S = Q K^T
        float s4[4][4];
        #pragma unroll
        for (int i = 0; i < 4; i++)
            #pragma unroll
            for (int j = 0; j < 4; j++) s4[i][j] = 0.f;

        #pragma unroll 8
        for (int kk = 0; kk < 64; kk++) {
            float a[4], bb[4];
            #pragma unroll
            for (int i = 0; i < 4; i++) a[i]  = Qs[ty * 4 + i][kk];
            #pragma unroll
            for (int j = 0; j < 4; j++) bb[j] = Ks[tx * 4 + j][kk];
            #pragma unroll
            for (int i = 0; i < 4; i++)
                #pragma unroll
                for (int j = 0; j < 4; j++)
                    s4[i][j] = fmaf(a[i], bb[j], s4[i][j]);
        }

        // scale + causal mask (only diagonal tile can have masked entries)
        #pragma unroll
        for (int i = 0; i < 4; i++)
            #pragma unroll
            for (int j = 0; j < 4; j++) {
                s4[i][j] *= scale;
                if (kt == qt && (tx * 4 + j) > (ty * 4 + i)) s4[i][j] = -1e30f;
            }

        // online softmax update
        float mt[4], rs[4], alpha[4];
        #pragma unroll
        for (int i = 0; i < 4; i++) {
            float v0 = fmaxf(fmaxf(s4[i][0], s4[i][1]), fmaxf(s4[i][2], s4[i][3]));
            #pragma unroll
            for (int off = 8; off >= 1; off >>= 1)
                v0 = fmaxf(v0, __shfl_xor_sync(0xffffffffu, v0, off));
            mt[i] = v0;
        }
        #pragma unroll
        for (int i = 0; i < 4; i++) {
            float mn = fmaxf(m[i], mt[i]);
            alpha[i] = __expf(m[i] - mn);
            m[i] = mn;
            float sum = 0.f;
            #pragma unroll
            for (int j = 0; j < 4; j++) {
                s4[i][j] = __expf(s4[i][j] - mn);
                sum += s4[i][j];
            }
            #pragma unroll
            for (int off = 8; off >= 1; off >>= 1)
                sum += __shfl_xor_sync(0xffffffffu, sum, off);
            rs[i] = sum;
        }
        #pragma unroll
        for (int i = 0; i < 4; i++) {
            l[i] = l[i] * alpha[i] + rs[i];
            #pragma unroll
            for (int j = 0; j < 4; j++) o[i][j] *= alpha[i];
        }

        // stage P to smem
        #pragma unroll
        for (int i = 0; i < 4; i++) {
            float4 pv = make_float4(s4[i][0], s4[i][1], s4[i][2], s4[i][3]);
            *reinterpret_cast<float4*>(&Ps[ty * 4 + i][tx * 4]) = pv;
        }
        __syncthreads();

        // O += P V
        #pragma unroll 8
        for (int kk = 0; kk < 64; kk++) {
            float a[4], bb[4];
            #pragma unroll
            for (int i = 0; i < 4; i++) a[i]  = Ps[ty * 4 + i][kk];
            #pragma unroll
            for (int j = 0; j < 4; j++) bb[j] = Vs[kk][tx * 4 + j];
            #pragma unroll
            for (int i = 0; i < 4; i++)
                #pragma unroll
                for (int j = 0; j < 4; j++)
                    o[i][j] = fmaf(a[i], bb[j], o[i][j]);
        }
    }

    // write out: y[b, t, h*64 + d]
    #pragma unroll
    for (int i = 0; i < 4; i++) {
        float inv = 1.f / l[i];
        float4 out = make_float4(o[i][0] * inv, o[i][1] * inv,
                                 o[i][2] * inv, o[i][3] * inv);
        *reinterpret_cast<float4*>(
            &g_y[(size_t)(b * TT + qt * 64 + ty * 4 + i) * EE + h * 64 + tx * 4]) = out;
    }
}

// ---------------------------------------------------------------------------
// kernel_launch
// inputs: x, cos, sin, Wq, Wk, Wv, Wo (all float32)
// ---------------------------------------------------------------------------
extern "C" void kernel_launch(void* const* d_in, const int* in_sizes, int n_in,
                              void* d_out, int out_size)
{
    const float* x   = (const float*)d_in[0];
    const float* cs  = (const float*)d_in[1];
    const float* sn  = (const float*)d_in[2];
    const float* Wq  = (const float*)d_in[3];
    const float* Wk  = (const float*)d_in[4];
    const float* Wv  = (const float*)d_in[5];
    const float* Wo  = (const float*)d_in[6];
    float* out = (float*)d_out;

    float *q, *k, *v, *y;
    cudaGetSymbolAddress((void**)&q, g_q);
    cudaGetSymbolAddress((void**)&k, g_k);
    cudaGetSymbolAddress((void**)&v, g_v);
    cudaGetSymbolAddress((void**)&y, g_y);

    // Flash kernel needs 65792 B dynamic smem (> 48K default)
    static const int FLASH_SMEM = (64*64 + 64*65 + 64*64 + 64*64) * 4;
    cudaFuncSetAttribute(flash_attn, cudaFuncAttributeMaxDynamicSharedMemorySize,
                         FLASH_SMEM);

    // Q/K/V projections: C = x @ W^T
    gemm_atb<<<dim3(EE / 64, MM / 64), 256>>>(x, Wq, q, MM, EE, EE);
    gemm_atb<<<dim3((KVH * HD) / 64, MM / 64), 256>>>(x, Wk, k, MM, KVH * HD, EE);
    gemm_atb<<<dim3((KVH * HD) / 64, MM / 64), 256>>>(x, Wv, v, MM, KVH * HD, EE);

    // RoPE on q and k
    {
        int nq = BB * TT * HH * 32;
        rope_kernel<<<(nq + 255) / 256, 256>>>(q, cs, sn, HH, nq);
        int nk = BB * TT * KVH * 32;
        rope_kernel<<<(nk + 255) / 256, 256>>>(k, cs, sn, KVH, nk);
    }

    // causal flash attention -> y
    flash_attn<<<dim3(TT / 64, HH, BB), 256, FLASH_SMEM>>>(q, k, v, y);

    // output projection: out = y @ Wo^T
    gemm_atb<<<dim3(EE / 64, MM / 64), 256>>>(y, Wo, out, MM, EE, EE);
}

// round 3
// speedup vs baseline: 1.7050x; 1.7050x over previous
#include <cuda_runtime.h>
#include <cuda_bf16.h>
#include <math.h>
#include <stdint.h>

// Problem constants
#define BB 2
#define TT 2048
#define EE 1024
#define HH 16
#define KVH 4
#define HD 64
#define GG 4           // H / KVH
#define MM (BB*TT)     // 4096 rows

// ---------------------------------------------------------------------------
// Device scratch (allocation-free rule: __device__ globals)
// ---------------------------------------------------------------------------
__device__ float g_q[MM*EE];            // 16 MiB
__device__ float g_k[MM*KVH*HD];        // 4 MiB
__device__ float g_v[MM*KVH*HD];        // 4 MiB
__device__ float g_y[MM*EE];            // 16 MiB

__device__ __nv_bfloat16 g_x_hi[MM*EE],      g_x_lo[MM*EE];
__device__ __nv_bfloat16 g_y_hi[MM*EE],      g_y_lo[MM*EE];
__device__ __nv_bfloat16 g_wq_hi[EE*EE],     g_wq_lo[EE*EE];
__device__ __nv_bfloat16 g_wk_hi[KVH*HD*EE], g_wk_lo[KVH*HD*EE];
__device__ __nv_bfloat16 g_wv_hi[KVH*HD*EE], g_wv_lo[KVH*HD*EE];
__device__ __nv_bfloat16 g_wo_hi[EE*EE],     g_wo_lo[EE*EE];

// ---------------------------------------------------------------------------
// PTX helpers: mma.sync + ldmatrix + cp.async (all legal on base sm_100)
// ---------------------------------------------------------------------------
__device__ __forceinline__ uint32_t smem_u32(const void* p) {
    uint32_t a;
    asm("{ .reg .u64 t; cvta.to.shared.u64 t, %1; cvt.u32.u64 %0, t; }"
        : "=r"(a) : "l"(p));
    return a;
}

#define LDSM4(r, addr) \
    asm volatile("ldmatrix.sync.aligned.m8n8.x4.shared.b16 {%0,%1,%2,%3}, [%4];" \
        : "=r"((r)[0]), "=r"((r)[1]), "=r"((r)[2]), "=r"((r)[3]) : "r"(addr))

#define MMA_BF16(d, a, b) \
    asm volatile("mma.sync.aligned.m16n8k16.row.col.f32.bf16.bf16.f32 " \
        "{%0,%1,%2,%3}, {%4,%5,%6,%7}, {%8,%9}, {%0,%1,%2,%3};" \
        : "+f"((d)[0]), "+f"((d)[1]), "+f"((d)[2]), "+f"((d)[3]) \
        : "r"((a)[0]), "r"((a)[1]), "r"((a)[2]), "r"((a)[3]), \
          "r"((b)[0]), "r"((b)[1]))

#define CP_ASYNC16(dst, src) \
    asm volatile("cp.async.cg.shared.global [%0], [%1], 16;" \
        :: "r"(dst), "l"(src))
#define CP_COMMIT() asm volatile("cp.async.commit_group;" ::: "memory")
#define CP_WAIT0()  asm volatile("cp.async.wait_group 0;" ::: "memory")

// ---------------------------------------------------------------------------
// split fp32 -> bf16 hi/lo (vectorized by 4)
// ---------------------------------------------------------------------------
__global__ void split_bf16x2(const float* __restrict__ in,
                             __nv_bfloat16* __restrict__ hi,
                             __nv_bfloat16* __restrict__ lo, int n4)
{
    int i = blockIdx.x * blockDim.x + threadIdx.x;
    if (i >= n4) return;
    float4 v = reinterpret_cast<const float4*>(in)[i];
    float f[4] = {v.x, v.y, v.z, v.w};
    __nv_bfloat16 h0 = __float2bfloat16(f[0]);
    __nv_bfloat16 h1 = __float2bfloat16(f[1]);
    __nv_bfloat16 h2 = __float2bfloat16(f[2]);
    __nv_bfloat16 h3 = __float2bfloat16(f[3]);
    __nv_bfloat16 l0 = __float2bfloat16(f[0] - __bfloat162float(h0));
    __nv_bfloat16 l1 = __float2bfloat16(f[1] - __bfloat162float(h1));
    __nv_bfloat16 l2 = __float2bfloat16(f[2] - __bfloat162float(h2));
    __nv_bfloat16 l3 = __float2bfloat16(f[3] - __bfloat162float(h3));
    uint32_t ph0 = (uint32_t)__bfloat16_as_ushort(h0) | ((uint32_t)__bfloat16_as_ushort(h1) << 16);
    uint32_t ph1 = (uint32_t)__bfloat16_as_ushort(h2) | ((uint32_t)__bfloat16_as_ushort(h3) << 16);
    uint32_t pl0 = (uint32_t)__bfloat16_as_ushort(l0) | ((uint32_t)__bfloat16_as_ushort(l1) << 16);
    uint32_t pl1 = (uint32_t)__bfloat16_as_ushort(l2) | ((uint32_t)__bfloat16_as_ushort(l3) << 16);
    reinterpret_cast<uint2*>(hi)[i] = make_uint2(ph0, ph1);
    reinterpret_cast<uint2*>(lo)[i] = make_uint2(pl0, pl1);
}

// ---------------------------------------------------------------------------
// mma.sync GEMM: C[M,N] = A[M,K] * W[N,K]^T, bf16x2 split (hh + hl + lh).
// CTA 128x128, BK=32, 256 threads (8 warps 2x4, warp tile 64x32).
// smem rows padded to 80B (conflict-free ldmatrix). Double-buffered cp.async.
// ---------------------------------------------------------------------------
// per-buffer layout (bytes): Ahi[128*80] Alo[128*80] Bhi[128*80] Blo[128*80]
#define TILE_BYTES   10240
#define BUF_BYTES    (4*TILE_BYTES)       // 40960
#define GEMM_SMEM    (2*BUF_BYTES)        // 81920

__device__ __forceinline__ void issue_tile(
    uint32_t sbuf,
    const __nv_bfloat16* __restrict__ Ahi, const __nv_bfloat16* __restrict__ Alo,
    const __nv_bfloat16* __restrict__ Bhi, const __nv_bfloat16* __restrict__ Blo,
    int m0, int n0, int k0, int K, int tid)
{
    #pragma unroll
    for (int it = 0; it < 2; it++) {
        int idx = tid + it * 256;        // 0..511
        int r   = idx >> 2;              // 0..127
        int c8  = idx & 3;               // 8-elem (16B) chunk
        uint32_t so = (uint32_t)(r * 80 + c8 * 16);
        size_t ga = (size_t)(m0 + r) * K + k0 + c8 * 8;
        size_t gb = (size_t)(n0 + r) * K + k0 + c8 * 8;
        CP_ASYNC16(sbuf + so,                 (const char*)(Ahi + ga));
        CP_ASYNC16(sbuf + TILE_BYTES + so,    (const char*)(Alo + ga));
        CP_ASYNC16(sbuf + 2*TILE_BYTES + so,  (const char*)(Bhi + gb));
        CP_ASYNC16(sbuf + 3*TILE_BYTES + so,  (const char*)(Blo + gb));
    }
}

__global__ __launch_bounds__(256) void gemm_mma(
    const __nv_bfloat16* __restrict__ Ahi, const __nv_bfloat16* __restrict__ Alo,
    const __nv_bfloat16* __restrict__ Bhi, const __nv_bfloat16* __restrict__ Blo,
    float* __restrict__ C, int M, int N, int K)
{
    extern __shared__ char sm[];
    const uint32_t sbase = smem_u32(sm);
    const int tid  = threadIdx.x;
    const int lane = tid & 31;
    const int wid  = tid >> 5;
    const int wm   = wid >> 2;          // 0..1 (M dir, 64 rows each)
    const int wn   = wid & 3;           // 0..3 (N dir, 32 cols each)
    const int m0   = blockIdx.y * 128;
    const int n0   = blockIdx.x * 128;

    float acc[4][4][4];
    #pragma unroll
    for (int i = 0; i < 4; i++)
        #pragma unroll
        for (int j = 0; j < 4; j++)
            #pragma unroll
            for (int r = 0; r < 4; r++) acc[i][j][r] = 0.f;

    // ldmatrix source addresses (within a buffer)
    const uint32_t a_row  = (uint32_t)(wm * 64 + (lane & 15));       // + mb*16
    const uint32_t a_k8   = (uint32_t)(lane >> 4);                    // 0/1
    const uint32_t b_row  = (uint32_t)(wn * 32 + (lane & 7) + ((lane >> 4) << 3)); // + nb*16
    const uint32_t b_k8   = (uint32_t)((lane >> 3) & 1);

    const int NK = K / 32;
    issue_tile(sbase, Ahi, Alo, Bhi, Blo, m0, n0, 0, K, tid);
    CP_COMMIT();

    for (int kt = 0; kt < NK; kt++) {
        CP_WAIT0();
        __syncthreads();
        if (kt + 1 < NK) {
            issue_tile(sbase + (uint32_t)((kt + 1) & 1) * BUF_BYTES,
                       Ahi, Alo, Bhi, Blo, m0, n0, (kt + 1) * 32, K, tid);
            CP_COMMIT();
        }
        const uint32_t buf = sbase + (uint32_t)(kt & 1) * BUF_BYTES;

        #pragma unroll
        for (int ks = 0; ks < 2; ks++) {
            uint32_t ah[4][4], al[4][4], bh[2][4], bl[2][4];
            #pragma unroll
            for (int mb = 0; mb < 4; mb++) {
                uint32_t addr = buf + (a_row + mb * 16) * 80
                                    + (ks * 2 + a_k8) * 16;
                LDSM4(ah[mb], addr);
                LDSM4(al[mb], addr + TILE_BYTES);
            }
            #pragma unroll
            for (int nb = 0; nb < 2; nb++) {
                uint32_t addr = buf + 2*TILE_BYTES
                                    + (b_row + nb * 16) * 80
                                    + (ks * 2 + b_k8) * 16;
                LDSM4(bh[nb], addr);
                LDSM4(bl[nb], addr + TILE_BYTES);
            }
            #pragma unroll
            for (int mb = 0; mb < 4; mb++) {
                #pragma unroll
                for (int n8 = 0; n8 < 4; n8++) {
                    uint32_t* Bh = &bh[n8 >> 1][(n8 & 1) * 2];
                    uint32_t* Bl = &bl[n8 >> 1][(n8 & 1) * 2];
                    MMA_BF16(acc[mb][n8], ah[mb], Bh);
                    MMA_BF16(acc[mb][n8], ah[mb], Bl);
                    MMA_BF16(acc[mb][n8], al[mb], Bh);
                }
            }
        }
    }

    // epilogue: direct global stores (float2, 8B aligned)
    #pragma unroll
    for (int mb = 0; mb < 4; mb++) {
        int row = m0 + wm * 64 + mb * 16 + (lane >> 2);
        #pragma unroll
        for (int n8 = 0; n8 < 4; n8++) {
            int col = n0 + wn * 32 + n8 * 8 + (lane & 3) * 2;
            *reinterpret_cast<float2*>(&C[(size_t)row * N + col]) =
                make_float2(acc[mb][n8][0], acc[mb][n8][1]);
            *reinterpret_cast<float2*>(&C[(size_t)(row + 8) * N + col]) =
                make_float2(acc[mb][n8][2], acc[mb][n8][3]);
        }
    }
}

// ---------------------------------------------------------------------------
// RoPE in-place: x layout [b*T + t][heads*64], cos/sin layout [b*T + t][64]
// ---------------------------------------------------------------------------
__global__ void rope_kernel(float* __restrict__ x,
                            const float* __restrict__ c,
                            const float* __restrict__ s,
                            int heads, int n)
{
    int idx = blockIdx.x * blockDim.x + threadIdx.x;
    if (idx >= n) return;
    int d  = idx & 31;
    int r  = idx >> 5;
    int h  = r % heads;
    int bt = r / heads;

    float* p = x + ((size_t)bt * heads + h) * 64;
    const float* cp = c + (size_t)bt * 64;
    const float* sp = s + (size_t)bt * 64;

    float x1 = p[d];
    float x2 = p[d + 32];
    p[d]      = x1 * cp[d]      - x2 * sp[d];
    p[d + 32] = x2 * cp[d + 32] + x1 * sp[d + 32];
}

// ---------------------------------------------------------------------------
// Causal flash attention, fp32, BM=BN=64, HD=64 (unchanged, known-correct)
// ---------------------------------------------------------------------------
__global__ __launch_bounds__(256) void flash_attn(
    const float* __restrict__ q, const float* __restrict__ k,
    const float* __restrict__ v, float* __restrict__ y)
{
    extern __shared__ float smf[];
    float (*Qs)[64] = (float(*)[64])(smf);
    float (*Ks)[65] = (float(*)[65])(smf + 64 * 64);
    float (*Vs)[64] = (float(*)[64])(smf + 64 * 64 + 64 * 65);
    float (*Ps)[64] = (float(*)[64])(smf + 64 * 64 + 64 * 65 + 64 * 64);

    const int tid = threadIdx.x;
    const int tx  = tid & 15;
    const int ty  = tid >> 4;
    const int qt  = blockIdx.x;
    const int h   = blockIdx.y;
    const int b   = blockIdx.z;
    const int kvh = h / GG;
    const float scale = 0.125f;   // 1/sqrt(64)

    #pragma unroll
    for (int p = 0; p < 16; p++) {
        int idx = tid + p * 256;
        int r = idx >> 6, c = idx & 63;
        Qs[r][c] = q[(size_t)(b * TT + qt * 64 + r) * EE + h * 64 + c];
    }

    float m[4], l[4], o[4][4];
    #pragma unroll
    for (int i = 0; i < 4; i++) {
        m[i] = -INFINITY; l[i] = 0.f;
        #pragma unroll
        for (int j = 0; j < 4; j++) o[i][j] = 0.f;
    }

    for (int kt = 0; kt <= qt; kt++) {
        __syncthreads();
        #pragma unroll
        for (int p = 0; p < 16; p++) {
            int idx = tid + p * 256;
            int r = idx >> 6, c = idx & 63;
            size_t base = (size_t)(b * TT + kt * 64 + r) * (KVH * HD) + kvh * 64 + c;
            Ks[r][c] = k[base];
            Vs[r][c] = v[base];
        }
        __syncthreads();

        float s4[4][4];
        #pragma unroll
        for (int i = 0; i < 4; i++)
            #pragma unroll
            for (int j = 0; j < 4; j++) s4[i][j] = 0.f;

        #pragma unroll 8
        for (int kk = 0; kk < 64; kk++) {
            float a[4], bb[4];
            #pragma unroll
            for (int i = 0; i < 4; i++) a[i]  = Qs[ty * 4 + i][kk];
            #pragma unroll
            for (int j = 0; j < 4; j++) bb[j] = Ks[tx * 4 + j][kk];
            #pragma unroll
            for (int i = 0; i < 4; i++)
                #pragma unroll
                for (int j = 0; j < 4; j++)
                    s4[i][j] = fmaf(a[i], bb[j], s4[i][j]);
        }

        #pragma unroll
        for (int i = 0; i < 4; i++)
            #pragma unroll
            for (int j = 0; j < 4; j++) {
                s4[i][j] *= scale;
                if (kt == qt && (tx * 4 + j) > (ty * 4 + i)) s4[i][j] = -1e30f;
            }

        float mt[4], rs[4], alpha[4];
        #pragma unroll
        for (int i = 0; i < 4; i++) {
            float v0 = fmaxf(fmaxf(s4[i][0], s4[i][1]), fmaxf(s4[i][2], s4[i][3]));
            #pragma unroll
            for (int off = 8; off >= 1; off >>= 1)
                v0 = fmaxf(v0, __shfl_xor_sync(0xffffffffu, v0, off));
            mt[i] = v0;
        }
        #pragma unroll
        for (int i = 0; i < 4; i++) {
            float mn = fmaxf(m[i], mt[i]);
            alpha[i] = __expf(m[i] - mn);
            m[i] = mn;
            float sum = 0.f;
            #pragma unroll
            for (int j = 0; j < 4; j++) {
                s4[i][j] = __expf(s4[i][j] - mn);
                sum += s4[i][j];
            }
            #pragma unroll
            for (int off = 8; off >= 1; off >>= 1)
                sum += __shfl_xor_sync(0xffffffffu, sum, off);
            rs[i] = sum;
        }
        #pragma unroll
        for (int i = 0; i < 4; i++) {
            l[i] = l[i] * alpha[i] + rs[i];
            #pragma unroll
            for (int j = 0; j < 4; j++) o[i][j] *= alpha[i];
        }

        #pragma unroll
        for (int i = 0; i < 4; i++) {
            float4 pv = make_float4(s4[i][0], s4[i][1], s4[i][2], s4[i][3]);
            *reinterpret_cast<float4*>(&Ps[ty * 4 + i][tx * 4]) = pv;
        }
        __syncthreads();

        #pragma unroll 8
        for (int kk = 0; kk < 64; kk++) {
            float a[4], bb[4];
            #pragma unroll
            for (int i = 0; i < 4; i++) a[i]  = Ps[ty * 4 + i][kk];
            #pragma unroll
            for (int j = 0; j < 4; j++) bb[j] = Vs[kk][tx * 4 + j];
            #pragma unroll
            for (int i = 0; i < 4; i++)
                #pragma unroll
                for (int j = 0; j < 4; j++)
                    o[i][j] = fmaf(a[i], bb[j], o[i][j]);
        }
    }

    #pragma unroll
    for (int i = 0; i < 4; i++) {
        float inv = 1.f / l[i];
        float4 out = make_float4(o[i][0] * inv, o[i][1] * inv,
                                 o[i][2] * inv, o[i][3] * inv);
        *reinterpret_cast<float4*>(
            &g_y[(size_t)(b * TT + qt * 64 + ty * 4 + i) * EE + h * 64 + tx * 4]) = out;
    }
}

// ---------------------------------------------------------------------------
// kernel_launch: x, cos, sin, Wq, Wk, Wv, Wo (all float32)
// ---------------------------------------------------------------------------
extern "C" void kernel_launch(void* const* d_in, const int* in_sizes, int n_in,
                              void* d_out, int out_size)
{
    const float* x   = (const float*)d_in[0];
    const float* cs  = (const float*)d_in[1];
    const float* sn  = (const float*)d_in[2];
    const float* Wq  = (const float*)d_in[3];
    const float* Wk  = (const float*)d_in[4];
    const float* Wv  = (const float*)d_in[5];
    const float* Wo  = (const float*)d_in[6];
    float* out = (float*)d_out;

    float *q, *k, *v, *y;
    cudaGetSymbolAddress((void**)&q, g_q);
    cudaGetSymbolAddress((void**)&k, g_k);
    cudaGetSymbolAddress((void**)&v, g_v);
    cudaGetSymbolAddress((void**)&y, g_y);

    __nv_bfloat16 *xh, *xl, *yh, *yl;
    __nv_bfloat16 *wqh, *wql, *wkh, *wkl, *wvh, *wvl, *woh, *wol;
    cudaGetSymbolAddress((void**)&xh,  g_x_hi);  cudaGetSymbolAddress((void**)&xl,  g_x_lo);
    cudaGetSymbolAddress((void**)&yh,  g_y_hi);  cudaGetSymbolAddress((void**)&yl,  g_y_lo);
    cudaGetSymbolAddress((void**)&wqh, g_wq_hi); cudaGetSymbolAddress((void**)&wql, g_wq_lo);
    cudaGetSymbolAddress((void**)&wkh, g_wk_hi); cudaGetSymbolAddress((void**)&wkl, g_wk_lo);
    cudaGetSymbolAddress((void**)&wvh, g_wv_hi); cudaGetSymbolAddress((void**)&wvl, g_wv_lo);
    cudaGetSymbolAddress((void**)&woh, g_wo_hi); cudaGetSymbolAddress((void**)&wol, g_wo_lo);

    static const int FLASH_SMEM = (64*64 + 64*65 + 64*64 + 64*64) * 4;
    cudaFuncSetAttribute(flash_attn, cudaFuncAttributeMaxDynamicSharedMemorySize,
                         FLASH_SMEM);
    cudaFuncSetAttribute(gemm_mma, cudaFuncAttributeMaxDynamicSharedMemorySize,
                         GEMM_SMEM);

    // splits
    {
        int n4;
        n4 = MM * EE / 4;        split_bf16x2<<<(n4 + 255) / 256, 256>>>(x,  xh,  xl,  n4);
        n4 = EE * EE / 4;        split_bf16x2<<<(n4 + 255) / 256, 256>>>(Wq, wqh, wql, n4);
        n4 = KVH * HD * EE / 4;  split_bf16x2<<<(n4 + 255) / 256, 256>>>(Wk, wkh, wkl, n4);
        n4 = KVH * HD * EE / 4;  split_bf16x2<<<(n4 + 255) / 256, 256>>>(Wv, wvh, wvl, n4);
        n4 = EE * EE / 4;        split_bf16x2<<<(n4 + 255) / 256, 256>>>(Wo, woh, wol, n4);
    }

    // projections on tensor cores (mma.sync)
    gemm_mma<<<dim3(EE / 128, MM / 128), 256, GEMM_SMEM>>>(xh, xl, wqh, wql, q, MM, EE, EE);
    gemm_mma<<<dim3((KVH*HD) / 128, MM / 128), 256, GEMM_SMEM>>>(xh, xl, wkh, wkl, k, MM, KVH*HD, EE);
    gemm_mma<<<dim3((KVH*HD) / 128, MM / 128), 256, GEMM_SMEM>>>(xh, xl, wvh, wvl, v, MM, KVH*HD, EE);

    // RoPE
    {
        int nq = BB * TT * HH * 32;
        rope_kernel<<<(nq + 255) / 256, 256>>>(q, cs, sn, HH, nq);
        int nk = BB * TT * KVH * 32;
        rope_kernel<<<(nk + 255) / 256, 256>>>(k, cs, sn, KVH, nk);
    }

    // attention
    flash_attn<<<dim3(TT / 64, HH, BB), 256, FLASH_SMEM>>>(q, k, v, y);

    // split y, output projection
    {
        int n4 = MM * EE / 4;
        split_bf16x2<<<(n4 + 255) / 256, 256>>>(y, yh, yl, n4);
    }
    gemm_mma<<<dim3(EE / 128, MM / 128), 256, GEMM_SMEM>>>(yh, yl, woh, wol, out, MM, EE, EE);
}

// round 4
// speedup vs baseline: 3.1496x; 1.8473x over previous
#include <cuda_runtime.h>
#include <cuda_bf16.h>
#include <math.h>
#include <stdint.h>

// Problem constants
#define BB 2
#define TT 2048
#define EE 1024
#define HH 16
#define KVH 4
#define HD 64
#define GG 4           // H / KVH
#define MM (BB*TT)     // 4096 rows

// ---------------------------------------------------------------------------
// Device scratch (allocation-free rule: __device__ globals)
// ---------------------------------------------------------------------------
__device__ float g_q[MM*EE];            // 16 MiB (fp32 q after proj)
__device__ float g_k[MM*KVH*HD];        // 4 MiB
__device__ float g_v[MM*KVH*HD];        // 4 MiB
__device__ float g_y[MM*EE];            // 16 MiB

__device__ __nv_bfloat16 g_x_hi[MM*EE],      g_x_lo[MM*EE];
__device__ __nv_bfloat16 g_y_hi[MM*EE],      g_y_lo[MM*EE];
__device__ __nv_bfloat16 g_wq_hi[EE*EE],     g_wq_lo[EE*EE];
__device__ __nv_bfloat16 g_wk_hi[KVH*HD*EE], g_wk_lo[KVH*HD*EE];
__device__ __nv_bfloat16 g_wv_hi[KVH*HD*EE], g_wv_lo[KVH*HD*EE];
__device__ __nv_bfloat16 g_wo_hi[EE*EE],     g_wo_lo[EE*EE];

__device__ __nv_bfloat16 g_qh[MM*EE],        g_ql[MM*EE];
__device__ __nv_bfloat16 g_kh[MM*KVH*HD],    g_kl[MM*KVH*HD];
__device__ __nv_bfloat16 g_vh[MM*KVH*HD],    g_vl[MM*KVH*HD];

// ---------------------------------------------------------------------------
// PTX helpers: mma.sync + ldmatrix + cp.async (base sm_100 ISA)
// ---------------------------------------------------------------------------
__device__ __forceinline__ uint32_t smem_u32(const void* p) {
    uint32_t a;
    asm("{ .reg .u64 t; cvta.to.shared.u64 t, %1; cvt.u32.u64 %0, t; }"
        : "=r"(a) : "l"(p));
    return a;
}

#define LDSM4(r, addr) \
    asm volatile("ldmatrix.sync.aligned.m8n8.x4.shared.b16 {%0,%1,%2,%3}, [%4];" \
        : "=r"((r)[0]), "=r"((r)[1]), "=r"((r)[2]), "=r"((r)[3]) : "r"(addr))

#define LDSM4T(r, addr) \
    asm volatile("ldmatrix.sync.aligned.m8n8.x4.trans.shared.b16 {%0,%1,%2,%3}, [%4];" \
        : "=r"((r)[0]), "=r"((r)[1]), "=r"((r)[2]), "=r"((r)[3]) : "r"(addr))

#define MMA_BF16(d, a, b) \
    asm volatile("mma.sync.aligned.m16n8k16.row.col.f32.bf16.bf16.f32 " \
        "{%0,%1,%2,%3}, {%4,%5,%6,%7}, {%8,%9}, {%0,%1,%2,%3};" \
        : "+f"((d)[0]), "+f"((d)[1]), "+f"((d)[2]), "+f"((d)[3]) \
        : "r"((a)[0]), "r"((a)[1]), "r"((a)[2]), "r"((a)[3]), \
          "r"((b)[0]), "r"((b)[1]))

#define CP_ASYNC16(dst, src) \
    asm volatile("cp.async.cg.shared.global [%0], [%1], 16;" \
        :: "r"(dst), "l"(src))
#define CP_COMMIT() asm volatile("cp.async.commit_group;" ::: "memory")
#define CP_WAIT0()  asm volatile("cp.async.wait_group 0;" ::: "memory")
#define CP_WAIT1()  asm volatile("cp.async.wait_group 1;" ::: "memory")

__device__ __forceinline__ uint32_t pack_bf16(float lo, float hi) {
    __nv_bfloat162 t = __float22bfloat162_rn(make_float2(lo, hi));
    return *reinterpret_cast<uint32_t*>(&t);
}

// ---------------------------------------------------------------------------
// split fp32 -> bf16 hi/lo (vectorized by 4)
// ---------------------------------------------------------------------------
__global__ void split_bf16x2(const float* __restrict__ in,
                             __nv_bfloat16* __restrict__ hi,
                             __nv_bfloat16* __restrict__ lo, int n4)
{
    int i = blockIdx.x * blockDim.x + threadIdx.x;
    if (i >= n4) return;
    float4 v = reinterpret_cast<const float4*>(in)[i];
    float f[4] = {v.x, v.y, v.z, v.w};
    __nv_bfloat16 h0 = __float2bfloat16(f[0]);
    __nv_bfloat16 h1 = __float2bfloat16(f[1]);
    __nv_bfloat16 h2 = __float2bfloat16(f[2]);
    __nv_bfloat16 h3 = __float2bfloat16(f[3]);
    __nv_bfloat16 l0 = __float2bfloat16(f[0] - __bfloat162float(h0));
    __nv_bfloat16 l1 = __float2bfloat16(f[1] - __bfloat162float(h1));
    __nv_bfloat16 l2 = __float2bfloat16(f[2] - __bfloat162float(h2));
    __nv_bfloat16 l3 = __float2bfloat16(f[3] - __bfloat162float(h3));
    uint32_t ph0 = (uint32_t)__bfloat16_as_ushort(h0) | ((uint32_t)__bfloat16_as_ushort(h1) << 16);
    uint32_t ph1 = (uint32_t)__bfloat16_as_ushort(h2) | ((uint32_t)__bfloat16_as_ushort(h3) << 16);
    uint32_t pl0 = (uint32_t)__bfloat16_as_ushort(l0) | ((uint32_t)__bfloat16_as_ushort(l1) << 16);
    uint32_t pl1 = (uint32_t)__bfloat16_as_ushort(l2) | ((uint32_t)__bfloat16_as_ushort(l3) << 16);
    reinterpret_cast<uint2*>(hi)[i] = make_uint2(ph0, ph1);
    reinterpret_cast<uint2*>(lo)[i] = make_uint2(pl0, pl1);
}

// ---------------------------------------------------------------------------
// RoPE + split: read fp32 (post-proj), apply rope, emit bf16 hi/lo.
// One thread per (bt, head, d in [0,32)).
// ---------------------------------------------------------------------------
__global__ void rope_split(const float* __restrict__ x,
                           const float* __restrict__ c,
                           const float* __restrict__ s,
                           __nv_bfloat16* __restrict__ hi,
                           __nv_bfloat16* __restrict__ lo,
                           int heads, int n)
{
    int idx = blockIdx.x * blockDim.x + threadIdx.x;
    if (idx >= n) return;
    int d  = idx & 31;
    int r  = idx >> 5;
    int h  = r % heads;
    int bt = r / heads;

    const float* p  = x + ((size_t)bt * heads + h) * 64;
    const float* cp = c + (size_t)bt * 64;
    const float* sp = s + (size_t)bt * 64;

    float x1 = p[d];
    float x2 = p[d + 32];
    float y1 = x1 * cp[d]      - x2 * sp[d];
    float y2 = x2 * cp[d + 32] + x1 * sp[d + 32];

    size_t o = ((size_t)bt * heads + h) * 64;
    __nv_bfloat16 h1 = __float2bfloat16(y1);
    __nv_bfloat16 h2 = __float2bfloat16(y2);
    hi[o + d]      = h1;
    hi[o + d + 32] = h2;
    lo[o + d]      = __float2bfloat16(y1 - __bfloat162float(h1));
    lo[o + d + 32] = __float2bfloat16(y2 - __bfloat162float(h2));
}

// ---------------------------------------------------------------------------
// mma.sync GEMM: C[M,N] = A[M,K] * W[N,K]^T, bf16x2 split (hh + hl + lh).
// (unchanged from R3 — validated)
// ---------------------------------------------------------------------------
#define TILE_BYTES   10240
#define BUF_BYTES    (4*TILE_BYTES)       // 40960
#define GEMM_SMEM    (2*BUF_BYTES)        // 81920

__device__ __forceinline__ void issue_tile(
    uint32_t sbuf,
    const __nv_bfloat16* __restrict__ Ahi, const __nv_bfloat16* __restrict__ Alo,
    const __nv_bfloat16* __restrict__ Bhi, const __nv_bfloat16* __restrict__ Blo,
    int m0, int n0, int k0, int K, int tid)
{
    #pragma unroll
    for (int it = 0; it < 2; it++) {
        int idx = tid + it * 256;        // 0..511
        int r   = idx >> 2;              // 0..127
        int c8  = idx & 3;               // 8-elem (16B) chunk
        uint32_t so = (uint32_t)(r * 80 + c8 * 16);
        size_t ga = (size_t)(m0 + r) * K + k0 + c8 * 8;
        size_t gb = (size_t)(n0 + r) * K + k0 + c8 * 8;
        CP_ASYNC16(sbuf + so,                 (const char*)(Ahi + ga));
        CP_ASYNC16(sbuf + TILE_BYTES + so,    (const char*)(Alo + ga));
        CP_ASYNC16(sbuf + 2*TILE_BYTES + so,  (const char*)(Bhi + gb));
        CP_ASYNC16(sbuf + 3*TILE_BYTES + so,  (const char*)(Blo + gb));
    }
}

__global__ __launch_bounds__(256) void gemm_mma(
    const __nv_bfloat16* __restrict__ Ahi, const __nv_bfloat16* __restrict__ Alo,
    const __nv_bfloat16* __restrict__ Bhi, const __nv_bfloat16* __restrict__ Blo,
    float* __restrict__ C, int M, int N, int K)
{
    extern __shared__ char sm[];
    const uint32_t sbase = smem_u32(sm);
    const int tid  = threadIdx.x;
    const int lane = tid & 31;
    const int wid  = tid >> 5;
    const int wm   = wid >> 2;
    const int wn   = wid & 3;
    const int m0   = blockIdx.y * 128;
    const int n0   = blockIdx.x * 128;

    float acc[4][4][4];
    #pragma unroll
    for (int i = 0; i < 4; i++)
        #pragma unroll
        for (int j = 0; j < 4; j++)
            #pragma unroll
            for (int r = 0; r < 4; r++) acc[i][j][r] = 0.f;

    const uint32_t a_row  = (uint32_t)(wm * 64 + (lane & 15));
    const uint32_t a_k8   = (uint32_t)(lane >> 4);
    const uint32_t b_row  = (uint32_t)(wn * 32 + (lane & 7) + ((lane >> 4) << 3));
    const uint32_t b_k8   = (uint32_t)((lane >> 3) & 1);

    const int NK = K / 32;
    issue_tile(sbase, Ahi, Alo, Bhi, Blo, m0, n0, 0, K, tid);
    CP_COMMIT();

    for (int kt = 0; kt < NK; kt++) {
        CP_WAIT0();
        __syncthreads();
        if (kt + 1 < NK) {
            issue_tile(sbase + (uint32_t)((kt + 1) & 1) * BUF_BYTES,
                       Ahi, Alo, Bhi, Blo, m0, n0, (kt + 1) * 32, K, tid);
            CP_COMMIT();
        }
        const uint32_t buf = sbase + (uint32_t)(kt & 1) * BUF_BYTES;

        #pragma unroll
        for (int ks = 0; ks < 2; ks++) {
            uint32_t ah[4][4], al[4][4], bh[2][4], bl[2][4];
            #pragma unroll
            for (int mb = 0; mb < 4; mb++) {
                uint32_t addr = buf + (a_row + mb * 16) * 80
                                    + (ks * 2 + a_k8) * 16;
                LDSM4(ah[mb], addr);
                LDSM4(al[mb], addr + TILE_BYTES);
            }
            #pragma unroll
            for (int nb = 0; nb < 2; nb++) {
                uint32_t addr = buf + 2*TILE_BYTES
                                    + (b_row + nb * 16) * 80
                                    + (ks * 2 + b_k8) * 16;
                LDSM4(bh[nb], addr);
                LDSM4(bl[nb], addr + TILE_BYTES);
            }
            #pragma unroll
            for (int mb = 0; mb < 4; mb++) {
                #pragma unroll
                for (int n8 = 0; n8 < 4; n8++) {
                    uint32_t* Bh = &bh[n8 >> 1][(n8 & 1) * 2];
                    uint32_t* Bl = &bl[n8 >> 1][(n8 & 1) * 2];
                    MMA_BF16(acc[mb][n8], ah[mb], Bh);
                    MMA_BF16(acc[mb][n8], ah[mb], Bl);
                    MMA_BF16(acc[mb][n8], al[mb], Bh);
                }
            }
        }
    }

    #pragma unroll
    for (int mb = 0; mb < 4; mb++) {
        int row = m0 + wm * 64 + mb * 16 + (lane >> 2);
        #pragma unroll
        for (int n8 = 0; n8 < 4; n8++) {
            int col = n0 + wn * 32 + n8 * 8 + (lane & 3) * 2;
            *reinterpret_cast<float2*>(&C[(size_t)row * N + col]) =
                make_float2(acc[mb][n8][0], acc[mb][n8][1]);
            *reinterpret_cast<float2*>(&C[(size_t)(row + 8) * N + col]) =
                make_float2(acc[mb][n8][2], acc[mb][n8][3]);
        }
    }
}

// ---------------------------------------------------------------------------
// Flash attention on mma.sync, bf16 hi/lo split, BM=BN=64, HD=64.
// 128 threads = 4 warps, each warp owns m16 rows. P kept in registers (FA2
// C-frag -> A-frag repack). K/V double-buffered via cp.async.
// ---------------------------------------------------------------------------
#define FROW      144                  // smem bytes per 64-col bf16 row
#define FARR      (64*FROW)            // 9216 bytes per array
#define SM_QH     0
#define SM_QL     FARR
#define SM_KV0    (2*FARR)             // 18432
#define KVBUF     (4*FARR)             // 36864 (kh, kl, vh, vl)
#define OFF_KH    0
#define OFF_KL    FARR
#define OFF_VH    (2*FARR)
#define OFF_VL    (3*FARR)
#define FLASH_SMEM (SM_KV0 + 2*KVBUF)  // 92160

__device__ __forceinline__ void flash_load_kv(
    uint32_t kb,
    const __nv_bfloat16* __restrict__ kh, const __nv_bfloat16* __restrict__ kl,
    const __nv_bfloat16* __restrict__ vh, const __nv_bfloat16* __restrict__ vl,
    int b, int kt, int kvh, int tid)
{
    #pragma unroll
    for (int it = 0; it < 4; it++) {
        int idx = tid + it * 128;       // 0..511
        int r   = idx >> 3;             // 0..63 (key row)
        int c   = idx & 7;              // 16B chunk
        size_t g = (size_t)(b * TT + kt * 64 + r) * (KVH * HD) + kvh * 64 + c * 8;
        uint32_t so = (uint32_t)(r * FROW + c * 16);
        CP_ASYNC16(kb + OFF_KH + so, (const char*)(kh + g));
        CP_ASYNC16(kb + OFF_KL + so, (const char*)(kl + g));
        CP_ASYNC16(kb + OFF_VH + so, (const char*)(vh + g));
        CP_ASYNC16(kb + OFF_VL + so, (const char*)(vl + g));
    }
}

__global__ __launch_bounds__(128) void flash_mma(
    const __nv_bfloat16* __restrict__ qh, const __nv_bfloat16* __restrict__ ql,
    const __nv_bfloat16* __restrict__ kh, const __nv_bfloat16* __restrict__ kl,
    const __nv_bfloat16* __restrict__ vh, const __nv_bfloat16* __restrict__ vl,
    float* __restrict__ y)
{
    extern __shared__ char sm[];
    const uint32_t sb = smem_u32(sm);
    const int tid  = threadIdx.x;
    const int lane = tid & 31;
    const int wid  = tid >> 5;
    const int qt   = blockIdx.x;
    const int h    = blockIdx.y;
    const int b    = blockIdx.z;
    const int kvh  = h / GG;

    // --- prologue: load Q tile (hi+lo), prefetch KV tile 0 ---
    #pragma unroll
    for (int it = 0; it < 4; it++) {
        int idx = tid + it * 128;
        int r   = idx >> 3;
        int c   = idx & 7;
        size_t g = (size_t)(b * TT + qt * 64 + r) * EE + h * 64 + c * 8;
        uint32_t so = (uint32_t)(r * FROW + c * 16);
        CP_ASYNC16(sb + SM_QH + so, (const char*)(qh + g));
        CP_ASYNC16(sb + SM_QL + so, (const char*)(ql + g));
    }
    CP_COMMIT();
    flash_load_kv(sb + SM_KV0, kh, kl, vh, vl, b, 0, kvh, tid);
    CP_COMMIT();

    CP_WAIT1();          // Q group done
    __syncthreads();

    // Q A-fragments, resident for whole CTA (per warp: m16 x k64)
    uint32_t qfh[4][4], qfl[4][4];
    {
        const uint32_t a_row = (uint32_t)(wid * 16 + (lane & 15));
        const uint32_t a_k8  = (uint32_t)(lane >> 4);
        #pragma unroll
        for (int ks = 0; ks < 4; ks++) {
            uint32_t addr = sb + SM_QH + a_row * FROW + (ks * 2 + a_k8) * 16;
            LDSM4(qfh[ks], addr);
            LDSM4(qfl[ks], addr + FARR);
        }
    }

    // K B-frag addressing (non-trans, [n][k] row-major):
    const uint32_t kb_row = (uint32_t)((lane & 7) + ((lane >> 4) << 3));
    const uint32_t kb_k8  = (uint32_t)((lane >> 3) & 1);
    // V B-frag addressing (trans, [k][n] row-major):
    const uint32_t vb_row = (uint32_t)((lane & 7) + (((lane >> 3) & 1) << 3));
    const uint32_t vb_col = (uint32_t)((lane >> 4) << 3);

    float oacc[8][4];
    #pragma unroll
    for (int nb = 0; nb < 8; nb++)
        #pragma unroll
        for (int j = 0; j < 4; j++) oacc[nb][j] = 0.f;
    float m0 = -INFINITY, m1 = -INFINITY, l0 = 0.f, l1 = 0.f;

    int cur = 0;
    for (int kt = 0; kt <= qt; kt++) {
        if (kt + 1 <= qt) {
            flash_load_kv(sb + SM_KV0 + (uint32_t)(cur ^ 1) * KVBUF,
                          kh, kl, vh, vl, b, kt + 1, kvh, tid);
            CP_COMMIT();
            CP_WAIT1();
        } else {
            CP_WAIT0();
        }
        __syncthreads();
        const uint32_t kvb = sb + SM_KV0 + (uint32_t)cur * KVBUF;

        // ---- S = Q K^T (3-term split), per warp m16 x n64 ----
        float sacc[8][4];
        #pragma unroll
        for (int nb = 0; nb < 8; nb++)
            #pragma unroll
            for (int j = 0; j < 4; j++) sacc[nb][j] = 0.f;

        #pragma unroll
        for (int ks = 0; ks < 4; ks++) {
            #pragma unroll
            for (int nb = 0; nb < 4; nb++) {
                uint32_t addr = kvb + OFF_KH + (kb_row + nb * 16) * FROW
                                            + (ks * 2 + kb_k8) * 16;
                uint32_t bh[4], bl[4];
                LDSM4(bh, addr);
                LDSM4(bl, addr + FARR);
                MMA_BF16(sacc[2*nb],   qfh[ks], bh);
                MMA_BF16(sacc[2*nb],   qfh[ks], bl);
                MMA_BF16(sacc[2*nb],   qfl[ks], bh);
                MMA_BF16(sacc[2*nb+1], qfh[ks], bh + 2);
                MMA_BF16(sacc[2*nb+1], qfh[ks], bl + 2);
                MMA_BF16(sacc[2*nb+1], qfl[ks], bh + 2);
            }
        }

        // ---- scale + causal mask ----
        #pragma unroll
        for (int nb = 0; nb < 8; nb++)
            #pragma unroll
            for (int j = 0; j < 4; j++) sacc[nb][j] *= 0.125f;
        if (kt == qt) {
            #pragma unroll
            for (int nb = 0; nb < 8; nb++)
                #pragma unroll
                for (int j = 0; j < 4; j++) {
                    int n_loc = nb * 8 + 2 * (lane & 3) + (j & 1);
                    int m_loc = wid * 16 + (lane >> 2) + ((j >> 1) << 3);
                    if (n_loc > m_loc) sacc[nb][j] = -1e30f;
                }
        }

        // ---- online softmax (rows: r0 = lane>>2, r1 = r0+8) ----
        float mx0 = -INFINITY, mx1 = -INFINITY;
        #pragma unroll
        for (int nb = 0; nb < 8; nb++) {
            mx0 = fmaxf(mx0, fmaxf(sacc[nb][0], sacc[nb][1]));
            mx1 = fmaxf(mx1, fmaxf(sacc[nb][2], sacc[nb][3]));
        }
        mx0 = fmaxf(mx0, __shfl_xor_sync(0xffffffffu, mx0, 1));
        mx0 = fmaxf(mx0, __shfl_xor_sync(0xffffffffu, mx0, 2));
        mx1 = fmaxf(mx1, __shfl_xor_sync(0xffffffffu, mx1, 1));
        mx1 = fmaxf(mx1, __shfl_xor_sync(0xffffffffu, mx1, 2));

        float mn0 = fmaxf(m0, mx0), mn1 = fmaxf(m1, mx1);
        float al0 = __expf(m0 - mn0), al1 = __expf(m1 - mn1);
        m0 = mn0; m1 = mn1;

        float sum0 = 0.f, sum1 = 0.f;
        #pragma unroll
        for (int nb = 0; nb < 8; nb++) {
            sacc[nb][0] = __expf(sacc[nb][0] - mn0);
            sacc[nb][1] = __expf(sacc[nb][1] - mn0);
            sacc[nb][2] = __expf(sacc[nb][2] - mn1);
            sacc[nb][3] = __expf(sacc[nb][3] - mn1);
            sum0 += sacc[nb][0] + sacc[nb][1];
            sum1 += sacc[nb][2] + sacc[nb][3];
        }
        sum0 += __shfl_xor_sync(0xffffffffu, sum0, 1);
        sum0 += __shfl_xor_sync(0xffffffffu, sum0, 2);
        sum1 += __shfl_xor_sync(0xffffffffu, sum1, 1);
        sum1 += __shfl_xor_sync(0xffffffffu, sum1, 2);
        l0 = l0 * al0 + sum0;
        l1 = l1 * al1 + sum1;

        #pragma unroll
        for (int nb = 0; nb < 8; nb++) {
            oacc[nb][0] *= al0; oacc[nb][1] *= al0;
            oacc[nb][2] *= al1; oacc[nb][3] *= al1;
        }

        // ---- pack P to bf16 hi/lo A-fragments (C-frag -> A-frag repack) ----
        uint32_t pfh[4][4], pfl[4][4];
        #pragma unroll
        for (int j16 = 0; j16 < 4; j16++) {
            float* c0 = sacc[2*j16];
            float* c1 = sacc[2*j16 + 1];
            float v0, v1, r0, r1;
            __nv_bfloat16 t0, t1;
            // a0: rows r0, keys 16j16 + {2q, 2q+1}
            v0 = c0[0]; v1 = c0[1];
            t0 = __float2bfloat16(v0); t1 = __float2bfloat16(v1);
            r0 = v0 - __bfloat162float(t0); r1 = v1 - __bfloat162float(t1);
            pfh[j16][0] = pack_bf16(v0, v1);   // rn-pack of hi parts
            pfl[j16][0] = pack_bf16(r0, r1);
            // a1: rows r0+8
            v0 = c0[2]; v1 = c0[3];
            t0 = __float2bfloat16(v0); t1 = __float2bfloat16(v1);
            r0 = v0 - __bfloat162float(t0); r1 = v1 - __bfloat162float(t1);
            pfh[j16][1] = pack_bf16(v0, v1);
            pfl[j16][1] = pack_bf16(r0, r1);
            // a2: rows r0, keys +8
            v0 = c1[0]; v1 = c1[1];
            t0 = __float2bfloat16(v0); t1 = __float2bfloat16(v1);
            r0 = v0 - __bfloat162float(t0); r1 = v1 - __bfloat162float(t1);
            pfh[j16][2] = pack_bf16(v0, v1);
            pfl[j16][2] = pack_bf16(r0, r1);
            // a3: rows r0+8, keys +8
            v0 = c1[2]; v1 = c1[3];
            t0 = __float2bfloat16(v0); t1 = __float2bfloat16(v1);
            r0 = v0 - __bfloat162float(t0); r1 = v1 - __bfloat162float(t1);
            pfh[j16][3] = pack_bf16(v0, v1);
            pfl[j16][3] = pack_bf16(r0, r1);
        }

        // ---- O += P V (3-term split); V via trans ldmatrix ----
        #pragma unroll
        for (int j16 = 0; j16 < 4; j16++) {
            #pragma unroll
            for (int nb = 0; nb < 4; nb++) {
                uint32_t addr = kvb + OFF_VH
                              + (j16 * 16 + vb_row) * FROW
                              + (nb * 16 + vb_col) * 2;
                uint32_t vhf[4], vlf[4];
                LDSM4T(vhf, addr);
                LDSM4T(vlf, addr + FARR);
                MMA_BF16(oacc[2*nb],   pfh[j16], vhf);
                MMA_BF16(oacc[2*nb],   pfh[j16], vlf);
                MMA_BF16(oacc[2*nb],   pfl[j16], vhf);
                MMA_BF16(oacc[2*nb+1], pfh[j16], vhf + 2);
                MMA_BF16(oacc[2*nb+1], pfh[j16], vlf + 2);
                MMA_BF16(oacc[2*nb+1], pfl[j16], vhf + 2);
            }
        }

        __syncthreads();   // all warps done with kvb before it is overwritten
        cur ^= 1;
    }

    // ---- epilogue: normalize + store ----
    float inv0 = 1.f / l0, inv1 = 1.f / l1;
    size_t row0 = (size_t)(b * TT + qt * 64 + wid * 16 + (lane >> 2));
    #pragma unroll
    for (int nb = 0; nb < 8; nb++) {
        size_t col = (size_t)(h * 64 + nb * 8 + 2 * (lane & 3));
        *reinterpret_cast<float2*>(&y[row0 * EE + col]) =
            make_float2(oacc[nb][0] * inv0, oacc[nb][1] * inv0);
        *reinterpret_cast<float2*>(&y[(row0 + 8) * EE + col]) =
            make_float2(oacc[nb][2] * inv1, oacc[nb][3] * inv1);
    }
}

// ---------------------------------------------------------------------------
// kernel_launch: x, cos, sin, Wq, Wk, Wv, Wo (all float32)
// ---------------------------------------------------------------------------
extern "C" void kernel_launch(void* const* d_in, const int* in_sizes, int n_in,
                              void* d_out, int out_size)
{
    const float* x   = (const float*)d_in[0];
    const float* cs  = (const float*)d_in[1];
    const float* sn  = (const float*)d_in[2];
    const float* Wq  = (const float*)d_in[3];
    const float* Wk  = (const float*)d_in[4];
    const float* Wv  = (const float*)d_in[5];
    const float* Wo  = (const float*)d_in[6];
    float* out = (float*)d_out;

    float *q, *k, *v, *y;
    cudaGetSymbolAddress((void**)&q, g_q);
    cudaGetSymbolAddress((void**)&k, g_k);
    cudaGetSymbolAddress((void**)&v, g_v);
    cudaGetSymbolAddress((void**)&y, g_y);

    __nv_bfloat16 *xh, *xl, *yh, *yl;
    __nv_bfloat16 *wqh, *wql, *wkh, *wkl, *wvh, *wvl, *woh, *wol;
    __nv_bfloat16 *qhp, *qlp, *khp, *klp, *vhp, *vlp;
    cudaGetSymbolAddress((void**)&xh,  g_x_hi);  cudaGetSymbolAddress((void**)&xl,  g_x_lo);
    cudaGetSymbolAddress((void**)&yh,  g_y_hi);  cudaGetSymbolAddress((void**)&yl,  g_y_lo);
    cudaGetSymbolAddress((void**)&wqh, g_wq_hi); cudaGetSymbolAddress((void**)&wql, g_wq_lo);
    cudaGetSymbolAddress((void**)&wkh, g_wk_hi); cudaGetSymbolAddress((void**)&wkl, g_wk_lo);
    cudaGetSymbolAddress((void**)&wvh, g_wv_hi); cudaGetSymbolAddress((void**)&wvl, g_wv_lo);
    cudaGetSymbolAddress((void**)&woh, g_wo_hi); cudaGetSymbolAddress((void**)&wol, g_wo_lo);
    cudaGetSymbolAddress((void**)&qhp, g_qh);    cudaGetSymbolAddress((void**)&qlp, g_ql);
    cudaGetSymbolAddress((void**)&khp, g_kh);    cudaGetSymbolAddress((void**)&klp, g_kl);
    cudaGetSymbolAddress((void**)&vhp, g_vh);    cudaGetSymbolAddress((void**)&vlp, g_vl);

    cudaFuncSetAttribute(gemm_mma, cudaFuncAttributeMaxDynamicSharedMemorySize,
                         GEMM_SMEM);
    cudaFuncSetAttribute(flash_mma, cudaFuncAttributeMaxDynamicSharedMemorySize,
                         FLASH_SMEM);

    // input splits
    {
        int n4;
        n4 = MM * EE / 4;        split_bf16x2<<<(n4 + 255) / 256, 256>>>(x,  xh,  xl,  n4);
        n4 = EE * EE / 4;        split_bf16x2<<<(n4 + 255) / 256, 256>>>(Wq, wqh, wql, n4);
        n4 = KVH * HD * EE / 4;  split_bf16x2<<<(n4 + 255) / 256, 256>>>(Wk, wkh, wkl, n4);
        n4 = KVH * HD * EE / 4;  split_bf16x2<<<(n4 + 255) / 256, 256>>>(Wv, wvh, wvl, n4);
        n4 = EE * EE / 4;        split_bf16x2<<<(n4 + 255) / 256, 256>>>(Wo, woh, wol, n4);
    }

    // projections (tensor cores)
    gemm_mma<<<dim3(EE / 128, MM / 128), 256, GEMM_SMEM>>>(xh, xl, wqh, wql, q, MM, EE, EE);
    gemm_mma<<<dim3((KVH*HD) / 128, MM / 128), 256, GEMM_SMEM>>>(xh, xl, wkh, wkl, k, MM, KVH*HD, EE);
    gemm_mma<<<dim3((KVH*HD) / 128, MM / 128), 256, GEMM_SMEM>>>(xh, xl, wvh, wvl, v, MM, KVH*HD, EE);

    // RoPE + bf16 hi/lo split for q, k; plain split for v
    {
        int nq = BB * TT * HH * 32;
        rope_split<<<(nq + 255) / 256, 256>>>(q, cs, sn, qhp, qlp, HH, nq);
        int nk = BB * TT * KVH * 32;
        rope_split<<<(nk + 255) / 256, 256>>>(k, cs, sn, khp, klp, KVH, nk);
        int n4 = MM * KVH * HD / 4;
        split_bf16x2<<<(n4 + 255) / 256, 256>>>(v, vhp, vlp, n4);
    }

    // attention (tensor cores)
    flash_mma<<<dim3(TT / 64, HH, BB), 128, FLASH_SMEM>>>(qhp, qlp, khp, klp, vhp, vlp, y);

    // split y, output projection
    {
        int n4 = MM * EE / 4;
        split_bf16x2<<<(n4 + 255) / 256, 256>>>(y, yh, yl, n4);
    }
    gemm_mma<<<dim3(EE / 128, MM / 128), 256, GEMM_SMEM>>>(yh, yl, woh, wol, out, MM, EE, EE);
}

// round 5
// speedup vs baseline: 3.4649x; 1.1001x over previous
#include <cuda_runtime.h>
#include <cuda_bf16.h>
#include <math.h>
#include <stdint.h>

// Problem constants
#define BB 2
#define TT 2048
#define EE 1024
#define HH 16
#define KVH 4
#define HD 64
#define GG 4           // H / KVH
#define MM (BB*TT)     // 4096 rows

// ---------------------------------------------------------------------------
// Device scratch (allocation-free rule: __device__ globals)
// ---------------------------------------------------------------------------
__device__ float g_q[MM*EE];            // 16 MiB (fp32 q after proj)
__device__ float g_k[MM*KVH*HD];        // 4 MiB
__device__ float g_v[MM*KVH*HD];        // 4 MiB
__device__ float g_y[MM*EE];            // 16 MiB

__device__ __nv_bfloat16 g_x_hi[MM*EE],      g_x_lo[MM*EE];
__device__ __nv_bfloat16 g_y_hi[MM*EE],      g_y_lo[MM*EE];
__device__ __nv_bfloat16 g_wq_hi[EE*EE],     g_wq_lo[EE*EE];
__device__ __nv_bfloat16 g_wk_hi[KVH*HD*EE], g_wk_lo[KVH*HD*EE];
__device__ __nv_bfloat16 g_wv_hi[KVH*HD*EE], g_wv_lo[KVH*HD*EE];
__device__ __nv_bfloat16 g_wo_hi[EE*EE],     g_wo_lo[EE*EE];

__device__ __nv_bfloat16 g_qh[MM*EE],        g_ql[MM*EE];
__device__ __nv_bfloat16 g_kh[MM*KVH*HD],    g_kl[MM*KVH*HD];
__device__ __nv_bfloat16 g_vh[MM*KVH*HD],    g_vl[MM*KVH*HD];

// ---------------------------------------------------------------------------
// PTX helpers: mma.sync + ldmatrix + cp.async (base sm_100 ISA)
// ---------------------------------------------------------------------------
__device__ __forceinline__ uint32_t smem_u32(const void* p) {
    uint32_t a;
    asm("{ .reg .u64 t; cvta.to.shared.u64 t, %1; cvt.u32.u64 %0, t; }"
        : "=r"(a) : "l"(p));
    return a;
}

#define LDSM4(r, addr) \
    asm volatile("ldmatrix.sync.aligned.m8n8.x4.shared.b16 {%0,%1,%2,%3}, [%4];" \
        : "=r"((r)[0]), "=r"((r)[1]), "=r"((r)[2]), "=r"((r)[3]) : "r"(addr))

#define LDSM4T(r, addr) \
    asm volatile("ldmatrix.sync.aligned.m8n8.x4.trans.shared.b16 {%0,%1,%2,%3}, [%4];" \
        : "=r"((r)[0]), "=r"((r)[1]), "=r"((r)[2]), "=r"((r)[3]) : "r"(addr))

#define MMA_BF16(d, a, b) \
    asm volatile("mma.sync.aligned.m16n8k16.row.col.f32.bf16.bf16.f32 " \
        "{%0,%1,%2,%3}, {%4,%5,%6,%7}, {%8,%9}, {%0,%1,%2,%3};" \
        : "+f"((d)[0]), "+f"((d)[1]), "+f"((d)[2]), "+f"((d)[3]) \
        : "r"((a)[0]), "r"((a)[1]), "r"((a)[2]), "r"((a)[3]), \
          "r"((b)[0]), "r"((b)[1]))

#define CP_ASYNC16(dst, src) \
    asm volatile("cp.async.cg.shared.global [%0], [%1], 16;" \
        :: "r"(dst), "l"(src))
#define CP_COMMIT() asm volatile("cp.async.commit_group;" ::: "memory")
#define CP_WAIT0()  asm volatile("cp.async.wait_group 0;" ::: "memory")
#define CP_WAIT1()  asm volatile("cp.async.wait_group 1;" ::: "memory")

__device__ __forceinline__ uint32_t pack_bf16(float lo, float hi) {
    __nv_bfloat162 t = __float22bfloat162_rn(make_float2(lo, hi));
    return *reinterpret_cast<uint32_t*>(&t);
}

// ---------------------------------------------------------------------------
// Batched split: 5 segments in one launch (blockIdx.y selects segment)
// ---------------------------------------------------------------------------
struct SplitArgs {
    const float*   in[5];
    __nv_bfloat16* hi[5];
    __nv_bfloat16* lo[5];
    int            n4[5];
};

__device__ __forceinline__ void split_one(const float* __restrict__ in,
                                          __nv_bfloat16* __restrict__ hi,
                                          __nv_bfloat16* __restrict__ lo, int i)
{
    float4 v = reinterpret_cast<const float4*>(in)[i];
    float f[4] = {v.x, v.y, v.z, v.w};
    __nv_bfloat16 h0 = __float2bfloat16(f[0]);
    __nv_bfloat16 h1 = __float2bfloat16(f[1]);
    __nv_bfloat16 h2 = __float2bfloat16(f[2]);
    __nv_bfloat16 h3 = __float2bfloat16(f[3]);
    __nv_bfloat16 l0 = __float2bfloat16(f[0] - __bfloat162float(h0));
    __nv_bfloat16 l1 = __float2bfloat16(f[1] - __bfloat162float(h1));
    __nv_bfloat16 l2 = __float2bfloat16(f[2] - __bfloat162float(h2));
    __nv_bfloat16 l3 = __float2bfloat16(f[3] - __bfloat162float(h3));
    uint32_t ph0 = (uint32_t)__bfloat16_as_ushort(h0) | ((uint32_t)__bfloat16_as_ushort(h1) << 16);
    uint32_t ph1 = (uint32_t)__bfloat16_as_ushort(h2) | ((uint32_t)__bfloat16_as_ushort(h3) << 16);
    uint32_t pl0 = (uint32_t)__bfloat16_as_ushort(l0) | ((uint32_t)__bfloat16_as_ushort(l1) << 16);
    uint32_t pl1 = (uint32_t)__bfloat16_as_ushort(l2) | ((uint32_t)__bfloat16_as_ushort(l3) << 16);
    reinterpret_cast<uint2*>(hi)[i] = make_uint2(ph0, ph1);
    reinterpret_cast<uint2*>(lo)[i] = make_uint2(pl0, pl1);
}

__global__ void split_all(SplitArgs a)
{
    int seg = blockIdx.y;
    int i   = blockIdx.x * blockDim.x + threadIdx.x;
    if (i >= a.n4[seg]) return;
    split_one(a.in[seg], a.hi[seg], a.lo[seg], i);
}

__global__ void split_bf16x2(const float* __restrict__ in,
                             __nv_bfloat16* __restrict__ hi,
                             __nv_bfloat16* __restrict__ lo, int n4)
{
    int i = blockIdx.x * blockDim.x + threadIdx.x;
    if (i >= n4) return;
    split_one(in, hi, lo, i);
}

// ---------------------------------------------------------------------------
// rope_all: y=0 -> q rope+split, y=1 -> k rope+split, y=2 -> v plain split
// ---------------------------------------------------------------------------
__global__ void rope_all(const float* __restrict__ q,
                         const float* __restrict__ k,
                         const float* __restrict__ v,
                         const float* __restrict__ c,
                         const float* __restrict__ s,
                         __nv_bfloat16* __restrict__ qh, __nv_bfloat16* __restrict__ ql,
                         __nv_bfloat16* __restrict__ kh, __nv_bfloat16* __restrict__ kl,
                         __nv_bfloat16* __restrict__ vh, __nv_bfloat16* __restrict__ vl)
{
    int seg = blockIdx.y;
    int idx = blockIdx.x * blockDim.x + threadIdx.x;
    if (seg == 2) {
        int n4 = MM * KVH * HD / 4;
        if (idx >= n4) return;
        split_one(v, vh, vl, idx);
        return;
    }
    const float* x = (seg == 0) ? q : k;
    __nv_bfloat16* hi = (seg == 0) ? qh : kh;
    __nv_bfloat16* lo = (seg == 0) ? ql : kl;
    int heads = (seg == 0) ? HH : KVH;
    int n = BB * TT * heads * 32;
    if (idx >= n) return;

    int d  = idx & 31;
    int r  = idx >> 5;
    int h  = r % heads;
    int bt = r / heads;

    const float* p  = x + ((size_t)bt * heads + h) * 64;
    const float* cp = c + (size_t)bt * 64;
    const float* sp = s + (size_t)bt * 64;

    float x1 = p[d];
    float x2 = p[d + 32];
    float y1 = x1 * cp[d]      - x2 * sp[d];
    float y2 = x2 * cp[d + 32] + x1 * sp[d + 32];

    size_t o = ((size_t)bt * heads + h) * 64;
    __nv_bfloat16 h1 = __float2bfloat16(y1);
    __nv_bfloat16 h2 = __float2bfloat16(y2);
    hi[o + d]      = h1;
    hi[o + d + 32] = h2;
    lo[o + d]      = __float2bfloat16(y1 - __bfloat162float(h1));
    lo[o + d + 32] = __float2bfloat16(y2 - __bfloat162float(h2));
}

// ---------------------------------------------------------------------------
// mma.sync GEMM body (validated R3): C[M,N] = A[M,K] * W[N,K]^T, bf16x2 split.
// CTA 128x128, BK=32, 256 threads (8 warps 2x4, warp tile 64x32).
// ---------------------------------------------------------------------------
#define TILE_BYTES   10240
#define BUF_BYTES    (4*TILE_BYTES)       // 40960
#define GEMM_SMEM    (2*BUF_BYTES)        // 81920

__device__ __forceinline__ void issue_tile(
    uint32_t sbuf,
    const __nv_bfloat16* __restrict__ Ahi, const __nv_bfloat16* __restrict__ Alo,
    const __nv_bfloat16* __restrict__ Bhi, const __nv_bfloat16* __restrict__ Blo,
    int m0, int n0, int k0, int K, int tid)
{
    #pragma unroll
    for (int it = 0; it < 2; it++) {
        int idx = tid + it * 256;        // 0..511
        int r   = idx >> 2;              // 0..127
        int c8  = idx & 3;               // 8-elem (16B) chunk
        uint32_t so = (uint32_t)(r * 80 + c8 * 16);
        size_t ga = (size_t)(m0 + r) * K + k0 + c8 * 8;
        size_t gb = (size_t)(n0 + r) * K + k0 + c8 * 8;
        CP_ASYNC16(sbuf + so,                 (const char*)(Ahi + ga));
        CP_ASYNC16(sbuf + TILE_BYTES + so,    (const char*)(Alo + ga));
        CP_ASYNC16(sbuf + 2*TILE_BYTES + so,  (const char*)(Bhi + gb));
        CP_ASYNC16(sbuf + 3*TILE_BYTES + so,  (const char*)(Blo + gb));
    }
}

__device__ __forceinline__ void gemm_body(
    uint32_t sbase,
    const __nv_bfloat16* __restrict__ Ahi, const __nv_bfloat16* __restrict__ Alo,
    const __nv_bfloat16* __restrict__ Bhi, const __nv_bfloat16* __restrict__ Blo,
    float* __restrict__ C, int M, int N, int K, int m0, int n0)
{
    const int tid  = threadIdx.x;
    const int lane = tid & 31;
    const int wid  = tid >> 5;
    const int wm   = wid >> 2;
    const int wn   = wid & 3;

    float acc[4][4][4];
    #pragma unroll
    for (int i = 0; i < 4; i++)
        #pragma unroll
        for (int j = 0; j < 4; j++)
            #pragma unroll
            for (int r = 0; r < 4; r++) acc[i][j][r] = 0.f;

    const uint32_t a_row  = (uint32_t)(wm * 64 + (lane & 15));
    const uint32_t a_k8   = (uint32_t)(lane >> 4);
    const uint32_t b_row  = (uint32_t)(wn * 32 + (lane & 7) + ((lane >> 4) << 3));
    const uint32_t b_k8   = (uint32_t)((lane >> 3) & 1);

    const int NK = K / 32;
    issue_tile(sbase, Ahi, Alo, Bhi, Blo, m0, n0, 0, K, tid);
    CP_COMMIT();

    for (int kt = 0; kt < NK; kt++) {
        CP_WAIT0();
        __syncthreads();
        if (kt + 1 < NK) {
            issue_tile(sbase + (uint32_t)((kt + 1) & 1) * BUF_BYTES,
                       Ahi, Alo, Bhi, Blo, m0, n0, (kt + 1) * 32, K, tid);
            CP_COMMIT();
        }
        const uint32_t buf = sbase + (uint32_t)(kt & 1) * BUF_BYTES;

        #pragma unroll
        for (int ks = 0; ks < 2; ks++) {
            uint32_t ah[4][4], al[4][4], bh[2][4], bl[2][4];
            #pragma unroll
            for (int mb = 0; mb < 4; mb++) {
                uint32_t addr = buf + (a_row + mb * 16) * 80
                                    + (ks * 2 + a_k8) * 16;
                LDSM4(ah[mb], addr);
                LDSM4(al[mb], addr + TILE_BYTES);
            }
            #pragma unroll
            for (int nb = 0; nb < 2; nb++) {
                uint32_t addr = buf + 2*TILE_BYTES
                                    + (b_row + nb * 16) * 80
                                    + (ks * 2 + b_k8) * 16;
                LDSM4(bh[nb], addr);
                LDSM4(bl[nb], addr + TILE_BYTES);
            }
            #pragma unroll
            for (int mb = 0; mb < 4; mb++) {
                #pragma unroll
                for (int n8 = 0; n8 < 4; n8++) {
                    uint32_t* Bh = &bh[n8 >> 1][(n8 & 1) * 2];
                    uint32_t* Bl = &bl[n8 >> 1][(n8 & 1) * 2];
                    MMA_BF16(acc[mb][n8], ah[mb], Bh);
                    MMA_BF16(acc[mb][n8], ah[mb], Bl);
                    MMA_BF16(acc[mb][n8], al[mb], Bh);
                }
            }
        }
    }

    #pragma unroll
    for (int mb = 0; mb < 4; mb++) {
        int row = m0 + wm * 64 + mb * 16 + (lane >> 2);
        #pragma unroll
        for (int n8 = 0; n8 < 4; n8++) {
            int col = n0 + wn * 32 + n8 * 8 + (lane & 3) * 2;
            *reinterpret_cast<float2*>(&C[(size_t)row * N + col]) =
                make_float2(acc[mb][n8][0], acc[mb][n8][1]);
            *reinterpret_cast<float2*>(&C[(size_t)(row + 8) * N + col]) =
                make_float2(acc[mb][n8][2], acc[mb][n8][3]);
        }
    }
}

__global__ __launch_bounds__(256) void gemm_mma(
    const __nv_bfloat16* __restrict__ Ahi, const __nv_bfloat16* __restrict__ Alo,
    const __nv_bfloat16* __restrict__ Bhi, const __nv_bfloat16* __restrict__ Blo,
    float* __restrict__ C, int M, int N, int K)
{
    extern __shared__ char sm[];
    gemm_body(smem_u32(sm), Ahi, Alo, Bhi, Blo, C, M, N, K,
              blockIdx.y * 128, blockIdx.x * 128);
}

// fused K/V projections: blockIdx.z selects weight/output pair
__global__ __launch_bounds__(256) void gemm_mma_kv(
    const __nv_bfloat16* __restrict__ Ahi, const __nv_bfloat16* __restrict__ Alo,
    const __nv_bfloat16* __restrict__ Wkh, const __nv_bfloat16* __restrict__ Wkl,
    const __nv_bfloat16* __restrict__ Wvh, const __nv_bfloat16* __restrict__ Wvl,
    float* __restrict__ Ck, float* __restrict__ Cv, int M, int N, int K)
{
    extern __shared__ char sm[];
    const __nv_bfloat16* Bh = blockIdx.z ? Wvh : Wkh;
    const __nv_bfloat16* Bl = blockIdx.z ? Wvl : Wkl;
    float* C = blockIdx.z ? Cv : Ck;
    gemm_body(smem_u32(sm), Ahi, Alo, Bh, Bl, C, M, N, K,
              blockIdx.y * 128, blockIdx.x * 128);
}

// ---------------------------------------------------------------------------
// Flash attention on mma.sync, bf16 hi/lo split, BM=BN=64, HD=64.
// Big-first causal scheduling: qt = gridDim.x-1-blockIdx.x.
// ---------------------------------------------------------------------------
#define FROW      144
#define FARR      (64*FROW)
#define SM_QH     0
#define SM_QL     FARR
#define SM_KV0    (2*FARR)
#define KVBUF     (4*FARR)
#define OFF_KH    0
#define OFF_KL    FARR
#define OFF_VH    (2*FARR)
#define OFF_VL    (3*FARR)
#define FLASH_SMEM (SM_KV0 + 2*KVBUF)  // 92160

__device__ __forceinline__ void flash_load_kv(
    uint32_t kb,
    const __nv_bfloat16* __restrict__ kh, const __nv_bfloat16* __restrict__ kl,
    const __nv_bfloat16* __restrict__ vh, const __nv_bfloat16* __restrict__ vl,
    int b, int kt, int kvh, int tid)
{
    #pragma unroll
    for (int it = 0; it < 4; it++) {
        int idx = tid + it * 128;
        int r   = idx >> 3;
        int c   = idx & 7;
        size_t g = (size_t)(b * TT + kt * 64 + r) * (KVH * HD) + kvh * 64 + c * 8;
        uint32_t so = (uint32_t)(r * FROW + c * 16);
        CP_ASYNC16(kb + OFF_KH + so, (const char*)(kh + g));
        CP_ASYNC16(kb + OFF_KL + so, (const char*)(kl + g));
        CP_ASYNC16(kb + OFF_VH + so, (const char*)(vh + g));
        CP_ASYNC16(kb + OFF_VL + so, (const char*)(vl + g));
    }
}

__global__ __launch_bounds__(128) void flash_mma(
    const __nv_bfloat16* __restrict__ qh, const __nv_bfloat16* __restrict__ ql,
    const __nv_bfloat16* __restrict__ kh, const __nv_bfloat16* __restrict__ kl,
    const __nv_bfloat16* __restrict__ vh, const __nv_bfloat16* __restrict__ vl,
    float* __restrict__ y)
{
    extern __shared__ char sm[];
    const uint32_t sb = smem_u32(sm);
    const int tid  = threadIdx.x;
    const int lane = tid & 31;
    const int wid  = tid >> 5;
    const int qt   = (int)(gridDim.x - 1 - blockIdx.x);   // big tiles first
    const int h    = blockIdx.y;
    const int b    = blockIdx.z;
    const int kvh  = h / GG;

    #pragma unroll
    for (int it = 0; it < 4; it++) {
        int idx = tid + it * 128;
        int r   = idx >> 3;
        int c   = idx & 7;
        size_t g = (size_t)(b * TT + qt * 64 + r) * EE + h * 64 + c * 8;
        uint32_t so = (uint32_t)(r * FROW + c * 16);
        CP_ASYNC16(sb + SM_QH + so, (const char*)(qh + g));
        CP_ASYNC16(sb + SM_QL + so, (const char*)(ql + g));
    }
    CP_COMMIT();
    flash_load_kv(sb + SM_KV0, kh, kl, vh, vl, b, 0, kvh, tid);
    CP_COMMIT();

    CP_WAIT1();
    __syncthreads();

    uint32_t qfh[4][4], qfl[4][4];
    {
        const uint32_t a_row = (uint32_t)(wid * 16 + (lane & 15));
        const uint32_t a_k8  = (uint32_t)(lane >> 4);
        #pragma unroll
        for (int ks = 0; ks < 4; ks++) {
            uint32_t addr = sb + SM_QH + a_row * FROW + (ks * 2 + a_k8) * 16;
            LDSM4(qfh[ks], addr);
            LDSM4(qfl[ks], addr + FARR);
        }
    }

    const uint32_t kb_row = (uint32_t)((lane & 7) + ((lane >> 4) << 3));
    const uint32_t kb_k8  = (uint32_t)((lane >> 3) & 1);
    const uint32_t vb_row = (uint32_t)((lane & 7) + (((lane >> 3) & 1) << 3));
    const uint32_t vb_col = (uint32_t)((lane >> 4) << 3);

    float oacc[8][4];
    #pragma unroll
    for (int nb = 0; nb < 8; nb++)
        #pragma unroll
        for (int j = 0; j < 4; j++) oacc[nb][j] = 0.f;
    float m0 = -INFINITY, m1 = -INFINITY, l0 = 0.f, l1 = 0.f;

    int cur = 0;
    for (int kt = 0; kt <= qt; kt++) {
        if (kt + 1 <= qt) {
            flash_load_kv(sb + SM_KV0 + (uint32_t)(cur ^ 1) * KVBUF,
                          kh, kl, vh, vl, b, kt + 1, kvh, tid);
            CP_COMMIT();
            CP_WAIT1();
        } else {
            CP_WAIT0();
        }
        __syncthreads();
        const uint32_t kvb = sb + SM_KV0 + (uint32_t)cur * KVBUF;

        float sacc[8][4];
        #pragma unroll
        for (int nb = 0; nb < 8; nb++)
            #pragma unroll
            for (int j = 0; j < 4; j++) sacc[nb][j] = 0.f;

        #pragma unroll
        for (int ks = 0; ks < 4; ks++) {
            #pragma unroll
            for (int nb = 0; nb < 4; nb++) {
                uint32_t addr = kvb + OFF_KH + (kb_row + nb * 16) * FROW
                                            + (ks * 2 + kb_k8) * 16;
                uint32_t bh[4], bl[4];
                LDSM4(bh, addr);
                LDSM4(bl, addr + FARR);
                MMA_BF16(sacc[2*nb],   qfh[ks], bh);
                MMA_BF16(sacc[2*nb],   qfh[ks], bl);
                MMA_BF16(sacc[2*nb],   qfl[ks], bh);
                MMA_BF16(sacc[2*nb+1], qfh[ks], bh + 2);
                MMA_BF16(sacc[2*nb+1], qfh[ks], bl + 2);
                MMA_BF16(sacc[2*nb+1], qfl[ks], bh + 2);
            }
        }

        #pragma unroll
        for (int nb = 0; nb < 8; nb++)
            #pragma unroll
            for (int j = 0; j < 4; j++) sacc[nb][j] *= 0.125f;
        if (kt == qt) {
            #pragma unroll
            for (int nb = 0; nb < 8; nb++)
                #pragma unroll
                for (int j = 0; j < 4; j++) {
                    int n_loc = nb * 8 + 2 * (lane & 3) + (j & 1);
                    int m_loc = wid * 16 + (lane >> 2) + ((j >> 1) << 3);
                    if (n_loc > m_loc) sacc[nb][j] = -1e30f;
                }
        }

        float mx0 = -INFINITY, mx1 = -INFINITY;
        #pragma unroll
        for (int nb = 0; nb < 8; nb++) {
            mx0 = fmaxf(mx0, fmaxf(sacc[nb][0], sacc[nb][1]));
            mx1 = fmaxf(mx1, fmaxf(sacc[nb][2], sacc[nb][3]));
        }
        mx0 = fmaxf(mx0, __shfl_xor_sync(0xffffffffu, mx0, 1));
        mx0 = fmaxf(mx0, __shfl_xor_sync(0xffffffffu, mx0, 2));
        mx1 = fmaxf(mx1, __shfl_xor_sync(0xffffffffu, mx1, 1));
        mx1 = fmaxf(mx1, __shfl_xor_sync(0xffffffffu, mx1, 2));

        float mn0 = fmaxf(m0, mx0), mn1 = fmaxf(m1, mx1);
        float al0 = __expf(m0 - mn0), al1 = __expf(m1 - mn1);
        m0 = mn0; m1 = mn1;

        float sum0 = 0.f, sum1 = 0.f;
        #pragma unroll
        for (int nb = 0; nb < 8; nb++) {
            sacc[nb][0] = __expf(sacc[nb][0] - mn0);
            sacc[nb][1] = __expf(sacc[nb][1] - mn0);
            sacc[nb][2] = __expf(sacc[nb][2] - mn1);
            sacc[nb][3] = __expf(sacc[nb][3] - mn1);
            sum0 += sacc[nb][0] + sacc[nb][1];
            sum1 += sacc[nb][2] + sacc[nb][3];
        }
        sum0 += __shfl_xor_sync(0xffffffffu, sum0, 1);
        sum0 += __shfl_xor_sync(0xffffffffu, sum0, 2);
        sum1 += __shfl_xor_sync(0xffffffffu, sum1, 1);
        sum1 += __shfl_xor_sync(0xffffffffu, sum1, 2);
        l0 = l0 * al0 + sum0;
        l1 = l1 * al1 + sum1;

        #pragma unroll
        for (int nb = 0; nb < 8; nb++) {
            oacc[nb][0] *= al0; oacc[nb][1] *= al0;
            oacc[nb][2] *= al1; oacc[nb][3] *= al1;
        }

        uint32_t pfh[4][4], pfl[4][4];
        #pragma unroll
        for (int j16 = 0; j16 < 4; j16++) {
            float* c0 = sacc[2*j16];
            float* c1 = sacc[2*j16 + 1];
            float v0, v1, r0, r1;
            __nv_bfloat16 t0, t1;
            v0 = c0[0]; v1 = c0[1];
            t0 = __float2bfloat16(v0); t1 = __float2bfloat16(v1);
            r0 = v0 - __bfloat162float(t0); r1 = v1 - __bfloat162float(t1);
            pfh[j16][0] = pack_bf16(v0, v1);
            pfl[j16][0] = pack_bf16(r0, r1);
            v0 = c0[2]; v1 = c0[3];
            t0 = __float2bfloat16(v0); t1 = __float2bfloat16(v1);
            r0 = v0 - __bfloat162float(t0); r1 = v1 - __bfloat162float(t1);
            pfh[j16][1] = pack_bf16(v0, v1);
            pfl[j16][1] = pack_bf16(r0, r1);
            v0 = c1[0]; v1 = c1[1];
            t0 = __float2bfloat16(v0); t1 = __float2bfloat16(v1);
            r0 = v0 - __bfloat162float(t0); r1 = v1 - __bfloat162float(t1);
            pfh[j16][2] = pack_bf16(v0, v1);
            pfl[j16][2] = pack_bf16(r0, r1);
            v0 = c1[2]; v1 = c1[3];
            t0 = __float2bfloat16(v0); t1 = __float2bfloat16(v1);
            r0 = v0 - __bfloat162float(t0); r1 = v1 - __bfloat162float(t1);
            pfh[j16][3] = pack_bf16(v0, v1);
            pfl[j16][3] = pack_bf16(r0, r1);
        }

        #pragma unroll
        for (int j16 = 0; j16 < 4; j16++) {
            #pragma unroll
            for (int nb = 0; nb < 4; nb++) {
                uint32_t addr = kvb + OFF_VH
                              + (j16 * 16 + vb_row) * FROW
                              + (nb * 16 + vb_col) * 2;
                uint32_t vhf[4], vlf[4];
                LDSM4T(vhf, addr);
                LDSM4T(vlf, addr + FARR);
                MMA_BF16(oacc[2*nb],   pfh[j16], vhf);
                MMA_BF16(oacc[2*nb],   pfh[j16], vlf);
                MMA_BF16(oacc[2*nb],   pfl[j16], vhf);
                MMA_BF16(oacc[2*nb+1], pfh[j16], vhf + 2);
                MMA_BF16(oacc[2*nb+1], pfh[j16], vlf + 2);
                MMA_BF16(oacc[2*nb+1], pfl[j16], vhf + 2);
            }
        }

        __syncthreads();
        cur ^= 1;
    }

    float inv0 = 1.f / l0, inv1 = 1.f / l1;
    size_t row0 = (size_t)(b * TT + qt * 64 + wid * 16 + (lane >> 2));
    #pragma unroll
    for (int nb = 0; nb < 8; nb++) {
        size_t col = (size_t)(h * 64 + nb * 8 + 2 * (lane & 3));
        *reinterpret_cast<float2*>(&y[row0 * EE + col]) =
            make_float2(oacc[nb][0] * inv0, oacc[nb][1] * inv0);
        *reinterpret_cast<float2*>(&y[(row0 + 8) * EE + col]) =
            make_float2(oacc[nb][2] * inv1, oacc[nb][3] * inv1);
    }
}

// ---------------------------------------------------------------------------
// kernel_launch: x, cos, sin, Wq, Wk, Wv, Wo (all float32)
// Launch order puts flash_mma 5th (ncu profiles the 5th launch).
// ---------------------------------------------------------------------------
extern "C" void kernel_launch(void* const* d_in, const int* in_sizes, int n_in,
                              void* d_out, int out_size)
{
    const float* x   = (const float*)d_in[0];
    const float* cs  = (const float*)d_in[1];
    const float* sn  = (const float*)d_in[2];
    const float* Wq  = (const float*)d_in[3];
    const float* Wk  = (const float*)d_in[4];
    const float* Wv  = (const float*)d_in[5];
    const float* Wo  = (const float*)d_in[6];
    float* out = (float*)d_out;

    float *q, *k, *v, *y;
    cudaGetSymbolAddress((void**)&q, g_q);
    cudaGetSymbolAddress((void**)&k, g_k);
    cudaGetSymbolAddress((void**)&v, g_v);
    cudaGetSymbolAddress((void**)&y, g_y);

    __nv_bfloat16 *xh, *xl, *yh, *yl;
    __nv_bfloat16 *wqh, *wql, *wkh, *wkl, *wvh, *wvl, *woh, *wol;
    __nv_bfloat16 *qhp, *qlp, *khp, *klp, *vhp, *vlp;
    cudaGetSymbolAddress((void**)&xh,  g_x_hi);  cudaGetSymbolAddress((void**)&xl,  g_x_lo);
    cudaGetSymbolAddress((void**)&yh,  g_y_hi);  cudaGetSymbolAddress((void**)&yl,  g_y_lo);
    cudaGetSymbolAddress((void**)&wqh, g_wq_hi); cudaGetSymbolAddress((void**)&wql, g_wq_lo);
    cudaGetSymbolAddress((void**)&wkh, g_wk_hi); cudaGetSymbolAddress((void**)&wkl, g_wk_lo);
    cudaGetSymbolAddress((void**)&wvh, g_wv_hi); cudaGetSymbolAddress((void**)&wvl, g_wv_lo);
    cudaGetSymbolAddress((void**)&woh, g_wo_hi); cudaGetSymbolAddress((void**)&wol, g_wo_lo);
    cudaGetSymbolAddress((void**)&qhp, g_qh);    cudaGetSymbolAddress((void**)&qlp, g_ql);
    cudaGetSymbolAddress((void**)&khp, g_kh);    cudaGetSymbolAddress((void**)&klp, g_kl);
    cudaGetSymbolAddress((void**)&vhp, g_vh);    cudaGetSymbolAddress((void**)&vlp, g_vl);

    cudaFuncSetAttribute(gemm_mma, cudaFuncAttributeMaxDynamicSharedMemorySize,
                         GEMM_SMEM);
    cudaFuncSetAttribute(gemm_mma_kv, cudaFuncAttributeMaxDynamicSharedMemorySize,
                         GEMM_SMEM);
    cudaFuncSetAttribute(flash_mma, cudaFuncAttributeMaxDynamicSharedMemorySize,
                         FLASH_SMEM);

    // #1: all 5 input splits in one launch
    {
        SplitArgs a;
        a.in[0] = x;  a.hi[0] = xh;  a.lo[0] = xl;  a.n4[0] = MM * EE / 4;
        a.in[1] = Wq; a.hi[1] = wqh; a.lo[1] = wql; a.n4[1] = EE * EE / 4;
        a.in[2] = Wk; a.hi[2] = wkh; a.lo[2] = wkl; a.n4[2] = KVH * HD * EE / 4;
        a.in[3] = Wv; a.hi[3] = wvh; a.lo[3] = wvl; a.n4[3] = KVH * HD * EE / 4;
        a.in[4] = Wo; a.hi[4] = woh; a.lo[4] = wol; a.n4[4] = EE * EE / 4;
        int maxb = (MM * EE / 4 + 255) / 256;   // 1024
        split_all<<<dim3(maxb, 5), 256>>>(a);
    }

    // #2: Q projection
    gemm_mma<<<dim3(EE / 128, MM / 128), 256, GEMM_SMEM>>>(xh, xl, wqh, wql, q, MM, EE, EE);

    // #3: K+V projections fused
    gemm_mma_kv<<<dim3((KVH*HD) / 128, MM / 128, 2), 256, GEMM_SMEM>>>(
        xh, xl, wkh, wkl, wvh, wvl, k, v, MM, KVH*HD, EE);

    // #4: rope q/k + v split in one launch
    {
        int maxb = (BB * TT * HH * 32 + 255) / 256;  // 8192
        rope_all<<<dim3(maxb, 3), 256>>>(q, k, v, cs, sn,
                                         qhp, qlp, khp, klp, vhp, vlp);
    }

    // #5: flash attention (profiled by ncu)
    flash_mma<<<dim3(TT / 64, HH, BB), 128, FLASH_SMEM>>>(qhp, qlp, khp, klp, vhp, vlp, y);

    // #6: split y
    {
        int n4 = MM * EE / 4;
        split_bf16x2<<<(n4 + 255) / 256, 256>>>(y, yh, yl, n4);
    }

    // #7: output projection
    gemm_mma<<<dim3(EE / 128, MM / 128), 256, GEMM_SMEM>>>(yh, yl, woh, wol, out, MM, EE, EE);
}